// round 15
// baseline (speedup 1.0000x reference)
#include <cuda_runtime.h>
#include <cuda_bf16.h>
#include <cstdint>
#include <cstddef>

#define N_NODES 20000
#define N_EDGES 160000
#define D_IN    512
#define D_LAT   512
#define D_OUT   256
#define L_LAYERS 3
#define ROW_U4  (D_LAT / 8)
#define WSZ     (D_LAT * D_LAT)

// ---------------------------------------------------------------------------
// Scratch statics. Activations live only as bf16 (hi, lo) pairs.
// ---------------------------------------------------------------------------
__device__ uint4 g_hhi[2][(size_t)N_NODES * ROW_U4];
__device__ uint4 g_hlo[2][(size_t)N_NODES * ROW_U4];
__device__ uint4 g_agghi[(size_t)N_NODES * ROW_U4];
__device__ uint4 g_agglo[(size_t)N_NODES * ROW_U4];
__device__ uint4 g_fhi[(size_t)N_NODES * ROW_U4];
__device__ uint4 g_flo[(size_t)N_NODES * ROW_U4];
__device__ __nv_bfloat16 g_whi[7 * WSZ + D_LAT * D_OUT];
__device__ __nv_bfloat16 g_wlo[7 * WSZ + D_LAT * D_OUT];
__device__ int    g_degi[N_NODES];
__device__ int    g_off[N_NODES + 1];
__device__ int    g_bsum[128];
__device__ int    g_cursor[N_NODES];
__device__ float2 g_csr[N_EDGES];
__device__ int    g_el64;

#define OFF_ENC      0
#define OFF_SELF(l)  ((1 + (l)) * WSZ)
#define OFF_NEIGH(l) ((4 + (l)) * WSZ)
#define OFF_OUT      (7 * WSZ)

__device__ __forceinline__ float2 bf2f(uint32_t u) {
    __nv_bfloat162 b = *(__nv_bfloat162*)&u;
    return __bfloat1622float2(b);
}
__device__ __forceinline__ void split2(float x, float y, uint32_t& hi, uint32_t& lo) {
    __nv_bfloat162 hb = __floats2bfloat162_rn(x, y);
    float2 hf = __bfloat1622float2(hb);
    __nv_bfloat162 lb = __floats2bfloat162_rn(x - hf.x, y - hf.y);
    hi = *(uint32_t*)&hb;
    lo = *(uint32_t*)&lb;
}

// ---------------------------------------------------------------------------
// Edge dtype detection (int64 per reference vs int32 per JAX x64-off)
// ---------------------------------------------------------------------------
__global__ void detect_kernel(const int* __restrict__ el32) {
    if (threadIdx.x == 0) {
        int any = 0;
        for (int i = 0; i < 256; i++) any |= el32[2 * i + 1];
        g_el64 = (any == 0) ? 1 : 0;
    }
}

__device__ __forceinline__ void load_edge(const void* __restrict__ el,
                                          int e, int& s, int& d) {
    if (g_el64) {
        const long long* p = (const long long*)el;
        s = (int)p[2 * e + 0];
        d = (int)p[2 * e + 1];
    } else {
        const int* p = (const int*)el;
        s = p[2 * e + 0];
        d = p[2 * e + 1];
    }
}

// ---------------------------------------------------------------------------
// CSR build
// ---------------------------------------------------------------------------
__global__ void degi_kernel(const void* __restrict__ el) {
    int e = blockIdx.x * blockDim.x + threadIdx.x;
    if (e < N_EDGES) {
        int s, d;
        load_edge(el, e, s, d);
        atomicAdd(&g_degi[d], 1);
    }
}

__global__ void scan1_kernel() {
    __shared__ int sm[256];
    int tid = threadIdx.x;
    int i = blockIdx.x * 256 + tid;
    int v = (i < N_NODES) ? g_degi[i] : 0;
    sm[tid] = v;
    __syncthreads();
    for (int o = 1; o < 256; o <<= 1) {
        int x = (tid >= o) ? sm[tid - o] : 0;
        __syncthreads();
        sm[tid] += x;
        __syncthreads();
    }
    if (i < N_NODES) g_off[i] = sm[tid] - v;
    if (tid == 255) g_bsum[blockIdx.x] = sm[255];
}

__global__ void scan2_kernel(int nblocks) {     // 1 block, 128 threads
    __shared__ int sm[128];
    int tid = threadIdx.x;
    int v = (tid < nblocks) ? g_bsum[tid] : 0;
    sm[tid] = v;
    __syncthreads();
    for (int o = 1; o < 128; o <<= 1) {
        int x = (tid >= o) ? sm[tid - o] : 0;
        __syncthreads();
        sm[tid] += x;
        __syncthreads();
    }
    if (tid < nblocks) g_bsum[tid] = sm[tid] - v;   // exclusive
}

__global__ void scan3_kernel() {
    int i = blockIdx.x * blockDim.x + threadIdx.x;
    if (i < N_NODES) {
        int o = g_off[i] + g_bsum[i >> 8];
        g_off[i] = o;
        g_cursor[i] = o;
    }
    if (i == 0) g_off[N_NODES] = N_EDGES;
}

__global__ void fill_kernel(const void* __restrict__ el) {
    int e = blockIdx.x * blockDim.x + threadIdx.x;
    if (e < N_EDGES) {
        int s, d;
        load_edge(el, e, s, d);
        float w = rsqrtf((float)(g_degi[d] + 1) * (float)(g_degi[s] + 1));
        int pos = atomicAdd(&g_cursor[d], 1);
        g_csr[pos] = make_float2(__int_as_float(s), w);
    }
}

// ---------------------------------------------------------------------------
// Feature split (also zero-fills g_degi — runs before degi_kernel)
// ---------------------------------------------------------------------------
__global__ void fsplit_kernel(const float* __restrict__ f) {
    int i = blockIdx.x * blockDim.x + threadIdx.x;
    if (i < N_NODES) g_degi[i] = 0;
    const int n = N_NODES * D_IN / 2;
    if (i < n) {
        float2 v = ((const float2*)f)[i];
        uint32_t hi, lo;
        split2(v.x, v.y, hi, lo);
        ((uint32_t*)g_fhi)[i] = hi;
        ((uint32_t*)g_flo)[i] = lo;
    }
}

// ---------------------------------------------------------------------------
// Fused weight prep (all 8 matrices, one launch): fp32 [K][N] -> split [N][K]
// ---------------------------------------------------------------------------
__global__ void wprep_all_kernel(const float* __restrict__ W_enc,
                                 const float* __restrict__ W_self,
                                 const float* __restrict__ W_neigh,
                                 const float* __restrict__ W_out) {
    __shared__ float t[32][33];
    const int z = blockIdx.z;
    const float* src;
    int dstOff, N = D_LAT;
    if (z == 0)      { src = W_enc;                      dstOff = OFF_ENC; }
    else if (z <= 3) { src = W_self + (size_t)(z - 1) * WSZ;  dstOff = OFF_SELF(z - 1); }
    else if (z <= 6) { src = W_neigh + (size_t)(z - 4) * WSZ; dstOff = OFF_NEIGH(z - 4); }
    else             { src = W_out;                      dstOff = OFF_OUT; N = D_OUT; }

    int n0 = blockIdx.x * 32;
    if (n0 >= N) return;
    int k0 = blockIdx.y * 32;
    int tx = threadIdx.x, ty = threadIdx.y;
#pragma unroll
    for (int j = 0; j < 4; j++)
        t[ty + j * 8][tx] = src[(size_t)(k0 + ty + j * 8) * N + n0 + tx];
    __syncthreads();
#pragma unroll
    for (int j = 0; j < 4; j++) {
        int n = n0 + ty + j * 8;
        int k = k0 + tx;
        float v = t[tx][ty + j * 8];
        __nv_bfloat16 hi = __float2bfloat16_rn(v);
        __nv_bfloat16 lo = __float2bfloat16_rn(v - __bfloat162float(hi));
        g_whi[(size_t)dstOff + (size_t)n * 512 + k] = hi;
        g_wlo[(size_t)dstOff + (size_t)n * 512 + k] = lo;
    }
}

// ---------------------------------------------------------------------------
// Gather: one warp per dst node; agg = sum w_e * (hi+lo)[src]
// ---------------------------------------------------------------------------
__global__ __launch_bounds__(256) void gather_kernel(int hsel) {
    int gw = (blockIdx.x * blockDim.x + threadIdx.x) >> 5;
    int lane = threadIdx.x & 31;
    if (gw >= N_NODES) return;
    int beg = g_off[gw], end = g_off[gw + 1];

    float acc[16];
#pragma unroll
    for (int i = 0; i < 16; i++) acc[i] = 0.0f;

    const uint4* Hh = g_hhi[hsel];
    const uint4* Hl = g_hlo[hsel];
    for (int i = beg; i < end; i++) {
        float2 er = g_csr[i];
        int s = __float_as_int(er.x);
        float w = er.y;
        const uint4* rh = Hh + (size_t)s * ROW_U4;
        const uint4* rl = Hl + (size_t)s * ROW_U4;
#pragma unroll
        for (int j = 0; j < 2; j++) {
            uint4 hv = rh[lane + 32 * j];
            uint4 lv = rl[lane + 32 * j];
            float2 a, b;
            a = bf2f(hv.x); b = bf2f(lv.x);
            acc[j * 8 + 0] += w * (a.x + b.x); acc[j * 8 + 1] += w * (a.y + b.y);
            a = bf2f(hv.y); b = bf2f(lv.y);
            acc[j * 8 + 2] += w * (a.x + b.x); acc[j * 8 + 3] += w * (a.y + b.y);
            a = bf2f(hv.z); b = bf2f(lv.z);
            acc[j * 8 + 4] += w * (a.x + b.x); acc[j * 8 + 5] += w * (a.y + b.y);
            a = bf2f(hv.w); b = bf2f(lv.w);
            acc[j * 8 + 6] += w * (a.x + b.x); acc[j * 8 + 7] += w * (a.y + b.y);
        }
    }
#pragma unroll
    for (int j = 0; j < 2; j++) {
        uint32_t ph[4], pl[4];
#pragma unroll
        for (int k = 0; k < 4; k++)
            split2(acc[j * 8 + k * 2], acc[j * 8 + k * 2 + 1], ph[k], pl[k]);
        g_agghi[(size_t)gw * ROW_U4 + lane + 32 * j] = make_uint4(ph[0], ph[1], ph[2], ph[3]);
        g_agglo[(size_t)gw * ROW_U4 + lane + 32 * j] = make_uint4(pl[0], pl[1], pl[2], pl[3]);
    }
}

// ---------------------------------------------------------------------------
// mma.sync GEMM, bf16 split-3 (dual-pass):  C = [relu]( A*W (+ Agg*W2) + bias )
// 128x128 tile, BK=32, 3-stage cp.async pipeline, ONE __syncthreads per
// chunk, prefetch HOISTED ahead of compute (barrier certifies the target
// stage is free), ldmatrix fragments, XOR-swizzled smem.
// ---------------------------------------------------------------------------
#define GEMM_SMEM 98304
#define TS(s, t) ((uint32_t)(s) * 32768u + (uint32_t)(t) * 8192u)

__device__ __forceinline__ void cp16(uint32_t d, const void* s, int sz) {
    asm volatile("cp.async.cg.shared.global [%0], [%1], 16, %2;\n"
                 :: "r"(d), "l"(s), "r"(sz));
}

#define LDM4(r, addr)                                                         \
    asm volatile("ldmatrix.sync.aligned.m8n8.x4.shared.b16 "                  \
                 "{%0, %1, %2, %3}, [%4];"                                    \
                 : "=r"((r)[0]), "=r"((r)[1]), "=r"((r)[2]), "=r"((r)[3])     \
                 : "r"(addr))

#define MMA4(d, a, b0v, b1v)                                                  \
    asm volatile(                                                             \
        "mma.sync.aligned.m16n8k16.row.col.f32.bf16.bf16.f32 "                \
        "{%0,%1,%2,%3}, {%4,%5,%6,%7}, {%8,%9}, {%0,%1,%2,%3};\n"             \
        : "+f"((d)[0]), "+f"((d)[1]), "+f"((d)[2]), "+f"((d)[3])              \
        : "r"((a)[0]), "r"((a)[1]), "r"((a)[2]), "r"((a)[3]),                 \
          "r"(b0v), "r"(b1v))

__global__ __launch_bounds__(256, 2) void gemm_kernel(
    int aSel, int wOff, int useAgg, int wOff2,
    const float* __restrict__ bias,
    int cSel, float* __restrict__ extC,
    int M, int Ntot, int doRelu)
{
    extern __shared__ char smem[];
    uint32_t sb = (uint32_t)__cvta_generic_to_shared(smem);
    const int tid = threadIdx.x;
    const int wid = tid >> 5, lane = tid & 31;
    const int wm = (wid >> 2) * 64, wn = (wid & 3) * 32;
    const int m0 = blockIdx.y * 128, n0 = blockIdx.x * 128;
    const int li = lane & 7, quad = lane >> 3;

    float acc[4][4][4];
#pragma unroll
    for (int a = 0; a < 4; a++)
#pragma unroll
        for (int b = 0; b < 4; b++)
#pragma unroll
            for (int d = 0; d < 4; d++) acc[a][b][d] = 0.0f;

    const int rA = (quad & 1) * 8 + li;
    const int sgA = quad >> 1;
    const int rB = (quad >> 1) * 8 + li;
    const int sgB = quad & 1;

    uint32_t offA[4], offB[2];
#pragma unroll
    for (int mt = 0; mt < 4; mt++) {
        int row = wm + mt * 16 + rA;
        offA[mt] = (uint32_t)(row * 32 + ((sgA ^ ((row >> 2) & 1)) * 16));
    }
#pragma unroll
    for (int ntp = 0; ntp < 2; ntp++) {
        int row = wn + ntp * 16 + rB;
        offB[ntp] = (uint32_t)(row * 32 + ((sgB ^ ((row >> 2) & 1)) * 16));
    }

    auto load_chunk = [&](int chunk, int stage) {
        const __nv_bfloat16 *Ah, *Al, *Bh, *Bl;
        if (chunk < 16) {
            Ah = (aSel == 2) ? (const __nv_bfloat16*)g_fhi
                             : (const __nv_bfloat16*)g_hhi[aSel];
            Al = (aSel == 2) ? (const __nv_bfloat16*)g_flo
                             : (const __nv_bfloat16*)g_hlo[aSel];
            Bh = g_whi + wOff;
            Bl = g_wlo + wOff;
        } else {
            Ah = (const __nv_bfloat16*)g_agghi;
            Al = (const __nv_bfloat16*)g_agglo;
            Bh = g_whi + wOff2;
            Bl = g_wlo + wOff2;
        }
        const int kk = (chunk & 15) * 32;
#pragma unroll
        for (int t = 0; t < 4; t++) {
            const __nv_bfloat16* src = (t == 0) ? Ah : (t == 1) ? Al
                                     : (t == 2) ? Bh : Bl;
            const bool isA = (t < 2);
#pragma unroll
            for (int i = 0; i < 2; i++) {
                int idx = tid + i * 256;
                int row = idx >> 2;
                int sub = (idx >> 1) & 1;
                int seg = idx & 1;
                int grow, valid;
                if (isA) {
                    int am = m0 + row;
                    valid = (am < M) ? 16 : 0;
                    grow = (am < M) ? am : 0;
                } else {
                    valid = 16;
                    grow = n0 + row;
                }
                const char* p = (const char*)(src + (size_t)grow * 512
                                              + kk + sub * 16 + seg * 8);
                uint32_t so = sb + TS(stage, t)
                            + (uint32_t)(sub * 4096 + row * 32
                                         + ((seg ^ ((row >> 2) & 1)) * 16));
                cp16(so, p, valid);
            }
        }
        asm volatile("cp.async.commit_group;\n");
    };

    const int NC = useAgg ? 32 : 16;
    load_chunk(0, 0);
    load_chunk(1, 1);

    for (int kt = 0; kt < NC; kt++) {
        int s = kt % 3;
        if (kt + 1 < NC) asm volatile("cp.async.wait_group 1;\n");
        else             asm volatile("cp.async.wait_group 0;\n");
        __syncthreads();   // chunk kt resident; all warps done reading kt-1

        // Prefetch kt+2 into stage (kt+2)%3 == (kt-1)%3 — freed by the
        // barrier above. Issuing BEFORE compute gives the cp.async a full
        // chunk of MMA work to hide its latency under.
        if (kt + 2 < NC) load_chunk(kt + 2, (kt + 2) % 3);

#pragma unroll
        for (int sub = 0; sub < 2; sub++) {
            uint32_t so = (uint32_t)(sub * 4096);
            uint32_t bh[2][4], bl[2][4];
#pragma unroll
            for (int ntp = 0; ntp < 2; ntp++) {
                LDM4(bh[ntp], sb + TS(s, 2) + so + offB[ntp]);
                LDM4(bl[ntp], sb + TS(s, 3) + so + offB[ntp]);
            }
#pragma unroll
            for (int mt = 0; mt < 4; mt++) {
                uint32_t ah[4], al[4];
                LDM4(ah, sb + TS(s, 0) + so + offA[mt]);
                LDM4(al, sb + TS(s, 1) + so + offA[mt]);
#pragma unroll
                for (int nt = 0; nt < 4; nt++) {
                    int ntp = nt >> 1, o = (nt & 1) * 2;
                    MMA4(acc[mt][nt], ah, bh[ntp][o], bh[ntp][o + 1]);
                    MMA4(acc[mt][nt], ah, bl[ntp][o], bl[ntp][o + 1]);
                    MMA4(acc[mt][nt], al, bh[ntp][o], bh[ntp][o + 1]);
                }
            }
        }
    }

    // Epilogue
    const int g = lane >> 2, c = lane & 3;
#pragma unroll
    for (int mt = 0; mt < 4; mt++) {
#pragma unroll
        for (int nt = 0; nt < 4; nt++) {
            int gn = n0 + wn + nt * 8 + 2 * c;
            float b0 = bias[gn], b1 = bias[gn + 1];
#pragma unroll
            for (int half = 0; half < 2; half++) {
                int grow = m0 + wm + mt * 16 + g + half * 8;
                if (grow >= M) continue;
                float v0 = acc[mt][nt][half * 2 + 0] + b0;
                float v1 = acc[mt][nt][half * 2 + 1] + b1;
                if (doRelu) { v0 = fmaxf(v0, 0.f); v1 = fmaxf(v1, 0.f); }
                if (cSel >= 0) {
                    uint32_t hi, lo;
                    split2(v0, v1, hi, lo);
                    size_t idx = (size_t)grow * (D_LAT / 2) + (gn >> 1);
                    ((uint32_t*)g_hhi[cSel])[idx] = hi;
                    ((uint32_t*)g_hlo[cSel])[idx] = lo;
                } else {
                    *(float2*)&extC[(size_t)grow * Ntot + gn] = make_float2(v0, v1);
                }
            }
        }
    }
}

// ---------------------------------------------------------------------------
// Launch
// ---------------------------------------------------------------------------
extern "C" void kernel_launch(void* const* d_in, const int* in_sizes, int n_in,
                              void* d_out, int out_size) {
    const float* features = (const float*)d_in[0];
    const void*  edges    = d_in[1];
    const float* W_enc    = (const float*)d_in[2];
    const float* b_enc    = (const float*)d_in[3];
    const float* W_self   = (const float*)d_in[4];
    const float* W_neigh  = (const float*)d_in[5];
    const float* b_comb   = (const float*)d_in[6];
    const float* W_out    = (const float*)d_in[7];
    const float* b_out    = (const float*)d_in[8];
    float*       out      = (float*)d_out;

    cudaFuncSetAttribute(gemm_kernel,
                         cudaFuncAttributeMaxDynamicSharedMemorySize, GEMM_SMEM);

    const int SCAN_BLOCKS = (N_NODES + 255) / 256;

    // detect + fsplit (also zeroes degi) -> CSR build; wprep independent
    detect_kernel<<<1, 32>>>((const int*)edges);
    fsplit_kernel<<<(N_NODES * D_IN / 2 + 255) / 256, 256>>>(features);
    degi_kernel<<<(N_EDGES + 255) / 256, 256>>>(edges);
    scan1_kernel<<<SCAN_BLOCKS, 256>>>();
    scan2_kernel<<<1, 128>>>(SCAN_BLOCKS);
    scan3_kernel<<<SCAN_BLOCKS, 256>>>();
    fill_kernel<<<(N_EDGES + 255) / 256, 256>>>(edges);
    wprep_all_kernel<<<dim3(16, 16, 8), dim3(32, 8)>>>(W_enc, W_self, W_neigh, W_out);

    const int MT = (N_NODES + 127) / 128;   // 157
    dim3 gLat(D_LAT / 128, MT);

    // Encoder: h[0] = features @ W_enc + b_enc
    gemm_kernel<<<gLat, 256, GEMM_SMEM>>>(2, OFF_ENC, 0, 0, b_enc, 0, nullptr,
                                          N_NODES, D_LAT, 0);

    int cur = 0;
    for (int l = 0; l < L_LAYERS; l++) {
        gather_kernel<<<(N_NODES * 32 + 255) / 256, 256>>>(cur);
        gemm_kernel<<<gLat, 256, GEMM_SMEM>>>(cur, OFF_SELF(l), 1, OFF_NEIGH(l),
                                              b_comb + (size_t)l * D_LAT,
                                              1 - cur, nullptr,
                                              N_NODES, D_LAT, 1);
        cur = 1 - cur;
    }

    // Output: out = h[cur] @ W_out + b_out
    dim3 gOut(D_OUT / 128, MT);
    gemm_kernel<<<gOut, 256, GEMM_SMEM>>>(cur, OFF_OUT, 0, 0, b_out, -1, out,
                                          N_NODES, D_OUT, 0);
}

// round 16
// speedup vs baseline: 1.3876x; 1.3876x over previous
#include <cuda_runtime.h>
#include <cuda_fp16.h>
#include <cstdint>
#include <cstddef>

#define N_NODES 20000
#define N_EDGES 160000
#define D_IN    512
#define D_LAT   512
#define D_OUT   256
#define L_LAYERS 3
#define ROW_U4  (D_LAT / 8)
#define WSZ     (D_LAT * D_LAT)

// ---------------------------------------------------------------------------
// Scratch statics. Activations live only as fp16 (hi, lo) pairs
// (x = hi + lo exact to ~eps_fp16^2). Weights are single fp16.
// ---------------------------------------------------------------------------
__device__ uint4 g_hhi[2][(size_t)N_NODES * ROW_U4];
__device__ uint4 g_hlo[2][(size_t)N_NODES * ROW_U4];
__device__ uint4 g_agghi[(size_t)N_NODES * ROW_U4];
__device__ uint4 g_agglo[(size_t)N_NODES * ROW_U4];
__device__ uint4 g_fhi[(size_t)N_NODES * ROW_U4];
__device__ uint4 g_flo[(size_t)N_NODES * ROW_U4];
__device__ __half g_wh[7 * WSZ + D_LAT * D_OUT];
__device__ int    g_degi[N_NODES];
__device__ int    g_off[N_NODES + 1];
__device__ int    g_bsum[128];
__device__ int    g_cursor[N_NODES];
__device__ float2 g_csr[N_EDGES];
__device__ int    g_el64;

#define OFF_ENC      0
#define OFF_SELF(l)  ((1 + (l)) * WSZ)
#define OFF_NEIGH(l) ((4 + (l)) * WSZ)
#define OFF_OUT      (7 * WSZ)

__device__ __forceinline__ float2 h2f(uint32_t u) {
    __half2 h = *(__half2*)&u;
    return __half22float2(h);
}
__device__ __forceinline__ void split2(float x, float y, uint32_t& hi, uint32_t& lo) {
    __half2 hb = __floats2half2_rn(x, y);
    float2 hf = __half22float2(hb);
    __half2 lb = __floats2half2_rn(x - hf.x, y - hf.y);
    hi = *(uint32_t*)&hb;
    lo = *(uint32_t*)&lb;
}

// ---------------------------------------------------------------------------
// Edge dtype detection (int64 per reference vs int32 per JAX x64-off)
// ---------------------------------------------------------------------------
__global__ void detect_kernel(const int* __restrict__ el32) {
    if (threadIdx.x == 0) {
        int any = 0;
        for (int i = 0; i < 256; i++) any |= el32[2 * i + 1];
        g_el64 = (any == 0) ? 1 : 0;
    }
}

__device__ __forceinline__ void load_edge(const void* __restrict__ el,
                                          int e, int& s, int& d) {
    if (g_el64) {
        const long long* p = (const long long*)el;
        s = (int)p[2 * e + 0];
        d = (int)p[2 * e + 1];
    } else {
        const int* p = (const int*)el;
        s = p[2 * e + 0];
        d = p[2 * e + 1];
    }
}

// ---------------------------------------------------------------------------
// CSR build
// ---------------------------------------------------------------------------
__global__ void degi_kernel(const void* __restrict__ el) {
    int e = blockIdx.x * blockDim.x + threadIdx.x;
    if (e < N_EDGES) {
        int s, d;
        load_edge(el, e, s, d);
        atomicAdd(&g_degi[d], 1);
    }
}

__global__ void scan1_kernel() {
    __shared__ int sm[256];
    int tid = threadIdx.x;
    int i = blockIdx.x * 256 + tid;
    int v = (i < N_NODES) ? g_degi[i] : 0;
    sm[tid] = v;
    __syncthreads();
    for (int o = 1; o < 256; o <<= 1) {
        int x = (tid >= o) ? sm[tid - o] : 0;
        __syncthreads();
        sm[tid] += x;
        __syncthreads();
    }
    if (i < N_NODES) g_off[i] = sm[tid] - v;
    if (tid == 255) g_bsum[blockIdx.x] = sm[255];
}

__global__ void scan2_kernel(int nblocks) {     // 1 block, 128 threads
    __shared__ int sm[128];
    int tid = threadIdx.x;
    int v = (tid < nblocks) ? g_bsum[tid] : 0;
    sm[tid] = v;
    __syncthreads();
    for (int o = 1; o < 128; o <<= 1) {
        int x = (tid >= o) ? sm[tid - o] : 0;
        __syncthreads();
        sm[tid] += x;
        __syncthreads();
    }
    if (tid < nblocks) g_bsum[tid] = sm[tid] - v;   // exclusive
}

__global__ void scan3_kernel() {
    int i = blockIdx.x * blockDim.x + threadIdx.x;
    if (i < N_NODES) {
        int o = g_off[i] + g_bsum[i >> 8];
        g_off[i] = o;
        g_cursor[i] = o;
    }
    if (i == 0) g_off[N_NODES] = N_EDGES;
}

__global__ void fill_kernel(const void* __restrict__ el) {
    int e = blockIdx.x * blockDim.x + threadIdx.x;
    if (e < N_EDGES) {
        int s, d;
        load_edge(el, e, s, d);
        float w = rsqrtf((float)(g_degi[d] + 1) * (float)(g_degi[s] + 1));
        int pos = atomicAdd(&g_cursor[d], 1);
        g_csr[pos] = make_float2(__int_as_float(s), w);
    }
}

// ---------------------------------------------------------------------------
// Feature split (also zero-fills g_degi — runs before degi_kernel)
// ---------------------------------------------------------------------------
__global__ void fsplit_kernel(const float* __restrict__ f) {
    int i = blockIdx.x * blockDim.x + threadIdx.x;
    if (i < N_NODES) g_degi[i] = 0;
    const int n = N_NODES * D_IN / 2;
    if (i < n) {
        float2 v = ((const float2*)f)[i];
        uint32_t hi, lo;
        split2(v.x, v.y, hi, lo);
        ((uint32_t*)g_fhi)[i] = hi;
        ((uint32_t*)g_flo)[i] = lo;
    }
}

// ---------------------------------------------------------------------------
// Fused weight prep (all 8 matrices, one launch): fp32 [K][N] -> fp16 [N][K]
// ---------------------------------------------------------------------------
__global__ void wprep_all_kernel(const float* __restrict__ W_enc,
                                 const float* __restrict__ W_self,
                                 const float* __restrict__ W_neigh,
                                 const float* __restrict__ W_out) {
    __shared__ float t[32][33];
    const int z = blockIdx.z;
    const float* src;
    int dstOff, N = D_LAT;
    if (z == 0)      { src = W_enc;                      dstOff = OFF_ENC; }
    else if (z <= 3) { src = W_self + (size_t)(z - 1) * WSZ;  dstOff = OFF_SELF(z - 1); }
    else if (z <= 6) { src = W_neigh + (size_t)(z - 4) * WSZ; dstOff = OFF_NEIGH(z - 4); }
    else             { src = W_out;                      dstOff = OFF_OUT; N = D_OUT; }

    int n0 = blockIdx.x * 32;
    if (n0 >= N) return;
    int k0 = blockIdx.y * 32;
    int tx = threadIdx.x, ty = threadIdx.y;
#pragma unroll
    for (int j = 0; j < 4; j++)
        t[ty + j * 8][tx] = src[(size_t)(k0 + ty + j * 8) * N + n0 + tx];
    __syncthreads();
#pragma unroll
    for (int j = 0; j < 4; j++) {
        int n = n0 + ty + j * 8;
        int k = k0 + tx;
        g_wh[(size_t)dstOff + (size_t)n * 512 + k] = __float2half_rn(t[tx][ty + j * 8]);
    }
}

// ---------------------------------------------------------------------------
// Gather: one warp per dst node; agg = sum w_e * (hi+lo)[src]
// ---------------------------------------------------------------------------
__global__ __launch_bounds__(256) void gather_kernel(int hsel) {
    int gw = (blockIdx.x * blockDim.x + threadIdx.x) >> 5;
    int lane = threadIdx.x & 31;
    if (gw >= N_NODES) return;
    int beg = g_off[gw], end = g_off[gw + 1];

    float acc[16];
#pragma unroll
    for (int i = 0; i < 16; i++) acc[i] = 0.0f;

    const uint4* Hh = g_hhi[hsel];
    const uint4* Hl = g_hlo[hsel];
    for (int i = beg; i < end; i++) {
        float2 er = g_csr[i];
        int s = __float_as_int(er.x);
        float w = er.y;
        const uint4* rh = Hh + (size_t)s * ROW_U4;
        const uint4* rl = Hl + (size_t)s * ROW_U4;
#pragma unroll
        for (int j = 0; j < 2; j++) {
            uint4 hv = rh[lane + 32 * j];
            uint4 lv = rl[lane + 32 * j];
            float2 a, b;
            a = h2f(hv.x); b = h2f(lv.x);
            acc[j * 8 + 0] += w * (a.x + b.x); acc[j * 8 + 1] += w * (a.y + b.y);
            a = h2f(hv.y); b = h2f(lv.y);
            acc[j * 8 + 2] += w * (a.x + b.x); acc[j * 8 + 3] += w * (a.y + b.y);
            a = h2f(hv.z); b = h2f(lv.z);
            acc[j * 8 + 4] += w * (a.x + b.x); acc[j * 8 + 5] += w * (a.y + b.y);
            a = h2f(hv.w); b = h2f(lv.w);
            acc[j * 8 + 6] += w * (a.x + b.x); acc[j * 8 + 7] += w * (a.y + b.y);
        }
    }
#pragma unroll
    for (int j = 0; j < 2; j++) {
        uint32_t ph[4], pl[4];
#pragma unroll
        for (int k = 0; k < 4; k++)
            split2(acc[j * 8 + k * 2], acc[j * 8 + k * 2 + 1], ph[k], pl[k]);
        g_agghi[(size_t)gw * ROW_U4 + lane + 32 * j] = make_uint4(ph[0], ph[1], ph[2], ph[3]);
        g_agglo[(size_t)gw * ROW_U4 + lane + 32 * j] = make_uint4(pl[0], pl[1], pl[2], pl[3]);
    }
}

// ---------------------------------------------------------------------------
// mma.sync GEMM, fp16 split-2 (dual-pass): C = [relu]( A*W (+ Agg*W2) + bias )
//   A = Ah + Al (fp16 pair, exact to eps^2); W single fp16.
//   acc = Ah*W + Al*W  (2 MMAs per k16; neglected error ~ eps_fp16 ~ 5e-4)
// 128x128 tile, BK=32, 3-stage cp.async, ONE __syncthreads per chunk,
// ldmatrix fragments, XOR-swizzled smem. 3 tiles/stage (Ah, Al, W) = 24KB.
// ---------------------------------------------------------------------------
#define GEMM_SMEM 73728
#define TS(s, t) ((uint32_t)(s) * 24576u + (uint32_t)(t) * 8192u)

__device__ __forceinline__ void cp16(uint32_t d, const void* s, int sz) {
    asm volatile("cp.async.cg.shared.global [%0], [%1], 16, %2;\n"
                 :: "r"(d), "l"(s), "r"(sz));
}

#define LDM4(r, addr)                                                         \
    asm volatile("ldmatrix.sync.aligned.m8n8.x4.shared.b16 "                  \
                 "{%0, %1, %2, %3}, [%4];"                                    \
                 : "=r"((r)[0]), "=r"((r)[1]), "=r"((r)[2]), "=r"((r)[3])     \
                 : "r"(addr))

#define MMA4(d, a, b0v, b1v)                                                  \
    asm volatile(                                                             \
        "mma.sync.aligned.m16n8k16.row.col.f32.f16.f16.f32 "                  \
        "{%0,%1,%2,%3}, {%4,%5,%6,%7}, {%8,%9}, {%0,%1,%2,%3};\n"             \
        : "+f"((d)[0]), "+f"((d)[1]), "+f"((d)[2]), "+f"((d)[3])              \
        : "r"((a)[0]), "r"((a)[1]), "r"((a)[2]), "r"((a)[3]),                 \
          "r"(b0v), "r"(b1v))

__global__ __launch_bounds__(256, 2) void gemm_kernel(
    int aSel, int wOff, int useAgg, int wOff2,
    const float* __restrict__ bias,
    int cSel, float* __restrict__ extC,
    int M, int Ntot, int doRelu)
{
    extern __shared__ char smem[];
    uint32_t sb = (uint32_t)__cvta_generic_to_shared(smem);
    const int tid = threadIdx.x;
    const int wid = tid >> 5, lane = tid & 31;
    const int wm = (wid >> 2) * 64, wn = (wid & 3) * 32;
    const int m0 = blockIdx.y * 128, n0 = blockIdx.x * 128;
    const int li = lane & 7, quad = lane >> 3;

    float acc[4][4][4];
#pragma unroll
    for (int a = 0; a < 4; a++)
#pragma unroll
        for (int b = 0; b < 4; b++)
#pragma unroll
            for (int d = 0; d < 4; d++) acc[a][b][d] = 0.0f;

    const int rA = (quad & 1) * 8 + li;
    const int sgA = quad >> 1;
    const int rB = (quad >> 1) * 8 + li;
    const int sgB = quad & 1;

    uint32_t offA[4], offB[2];
#pragma unroll
    for (int mt = 0; mt < 4; mt++) {
        int row = wm + mt * 16 + rA;
        offA[mt] = (uint32_t)(row * 32 + ((sgA ^ ((row >> 2) & 1)) * 16));
    }
#pragma unroll
    for (int ntp = 0; ntp < 2; ntp++) {
        int row = wn + ntp * 16 + rB;
        offB[ntp] = (uint32_t)(row * 32 + ((sgB ^ ((row >> 2) & 1)) * 16));
    }

    auto load_chunk = [&](int chunk, int stage) {
        const __half *Ah, *Al, *Bh;
        if (chunk < 16) {
            Ah = (aSel == 2) ? (const __half*)g_fhi : (const __half*)g_hhi[aSel];
            Al = (aSel == 2) ? (const __half*)g_flo : (const __half*)g_hlo[aSel];
            Bh = g_wh + wOff;
        } else {
            Ah = (const __half*)g_agghi;
            Al = (const __half*)g_agglo;
            Bh = g_wh + wOff2;
        }
        const int kk = (chunk & 15) * 32;
#pragma unroll
        for (int t = 0; t < 3; t++) {
            const __half* src = (t == 0) ? Ah : (t == 1) ? Al : Bh;
            const bool isA = (t < 2);
#pragma unroll
            for (int i = 0; i < 2; i++) {
                int idx = tid + i * 256;
                int row = idx >> 2;
                int sub = (idx >> 1) & 1;
                int seg = idx & 1;
                int grow, valid;
                if (isA) {
                    int am = m0 + row;
                    valid = (am < M) ? 16 : 0;
                    grow = (am < M) ? am : 0;
                } else {
                    valid = 16;
                    grow = n0 + row;
                }
                const char* p = (const char*)(src + (size_t)grow * 512
                                              + kk + sub * 16 + seg * 8);
                uint32_t so = sb + TS(stage, t)
                            + (uint32_t)(sub * 4096 + row * 32
                                         + ((seg ^ ((row >> 2) & 1)) * 16));
                cp16(so, p, valid);
            }
        }
        asm volatile("cp.async.commit_group;\n");
    };

    const int NC = useAgg ? 32 : 16;
    load_chunk(0, 0);
    load_chunk(1, 1);

    for (int kt = 0; kt < NC; kt++) {
        int s = kt % 3;
        if (kt + 1 < NC) asm volatile("cp.async.wait_group 1;\n");
        else             asm volatile("cp.async.wait_group 0;\n");
        __syncthreads();   // chunk kt resident; all warps done reading kt-1

#pragma unroll
        for (int sub = 0; sub < 2; sub++) {
            uint32_t so = (uint32_t)(sub * 4096);
            uint32_t bh[2][4];
#pragma unroll
            for (int ntp = 0; ntp < 2; ntp++)
                LDM4(bh[ntp], sb + TS(s, 2) + so + offB[ntp]);
#pragma unroll
            for (int mt = 0; mt < 4; mt++) {
                uint32_t ah[4], al[4];
                LDM4(ah, sb + TS(s, 0) + so + offA[mt]);
                LDM4(al, sb + TS(s, 1) + so + offA[mt]);
#pragma unroll
                for (int nt = 0; nt < 4; nt++) {
                    int ntp = nt >> 1, o = (nt & 1) * 2;
                    MMA4(acc[mt][nt], ah, bh[ntp][o], bh[ntp][o + 1]);
                    MMA4(acc[mt][nt], al, bh[ntp][o], bh[ntp][o + 1]);
                }
            }
        }
        if (kt + 2 < NC) load_chunk(kt + 2, (kt + 2) % 3);
    }

    // Epilogue
    const int g = lane >> 2, c = lane & 3;
#pragma unroll
    for (int mt = 0; mt < 4; mt++) {
#pragma unroll
        for (int nt = 0; nt < 4; nt++) {
            int gn = n0 + wn + nt * 8 + 2 * c;
            float b0 = bias[gn], b1 = bias[gn + 1];
#pragma unroll
            for (int half = 0; half < 2; half++) {
                int grow = m0 + wm + mt * 16 + g + half * 8;
                if (grow >= M) continue;
                float v0 = acc[mt][nt][half * 2 + 0] + b0;
                float v1 = acc[mt][nt][half * 2 + 1] + b1;
                if (doRelu) { v0 = fmaxf(v0, 0.f); v1 = fmaxf(v1, 0.f); }
                if (cSel >= 0) {
                    uint32_t hi, lo;
                    split2(v0, v1, hi, lo);
                    size_t idx = (size_t)grow * (D_LAT / 2) + (gn >> 1);
                    ((uint32_t*)g_hhi[cSel])[idx] = hi;
                    ((uint32_t*)g_hlo[cSel])[idx] = lo;
                } else {
                    *(float2*)&extC[(size_t)grow * Ntot + gn] = make_float2(v0, v1);
                }
            }
        }
    }
}

// ---------------------------------------------------------------------------
// Launch
// ---------------------------------------------------------------------------
extern "C" void kernel_launch(void* const* d_in, const int* in_sizes, int n_in,
                              void* d_out, int out_size) {
    const float* features = (const float*)d_in[0];
    const void*  edges    = d_in[1];
    const float* W_enc    = (const float*)d_in[2];
    const float* b_enc    = (const float*)d_in[3];
    const float* W_self   = (const float*)d_in[4];
    const float* W_neigh  = (const float*)d_in[5];
    const float* b_comb   = (const float*)d_in[6];
    const float* W_out    = (const float*)d_in[7];
    const float* b_out    = (const float*)d_in[8];
    float*       out      = (float*)d_out;

    cudaFuncSetAttribute(gemm_kernel,
                         cudaFuncAttributeMaxDynamicSharedMemorySize, GEMM_SMEM);

    const int SCAN_BLOCKS = (N_NODES + 255) / 256;

    // detect + fsplit (also zeroes degi) -> CSR build; wprep independent
    detect_kernel<<<1, 32>>>((const int*)edges);
    fsplit_kernel<<<(N_NODES * D_IN / 2 + 255) / 256, 256>>>(features);
    degi_kernel<<<(N_EDGES + 255) / 256, 256>>>(edges);
    scan1_kernel<<<SCAN_BLOCKS, 256>>>();
    scan2_kernel<<<1, 128>>>(SCAN_BLOCKS);
    scan3_kernel<<<SCAN_BLOCKS, 256>>>();
    fill_kernel<<<(N_EDGES + 255) / 256, 256>>>(edges);
    wprep_all_kernel<<<dim3(16, 16, 8), dim3(32, 8)>>>(W_enc, W_self, W_neigh, W_out);

    const int MT = (N_NODES + 127) / 128;   // 157
    dim3 gLat(D_LAT / 128, MT);

    // Encoder: h[0] = features @ W_enc + b_enc
    gemm_kernel<<<gLat, 256, GEMM_SMEM>>>(2, OFF_ENC, 0, 0, b_enc, 0, nullptr,
                                          N_NODES, D_LAT, 0);

    int cur = 0;
    for (int l = 0; l < L_LAYERS; l++) {
        gather_kernel<<<(N_NODES * 32 + 255) / 256, 256>>>(cur);
        gemm_kernel<<<gLat, 256, GEMM_SMEM>>>(cur, OFF_SELF(l), 1, OFF_NEIGH(l),
                                              b_comb + (size_t)l * D_LAT,
                                              1 - cur, nullptr,
                                              N_NODES, D_LAT, 1);
        cur = 1 - cur;
    }

    // Output: out = h[cur] @ W_out + b_out
    dim3 gOut(D_OUT / 128, MT);
    gemm_kernel<<<gOut, 256, GEMM_SMEM>>>(cur, OFF_OUT, 0, 0, b_out, -1, out,
                                          N_NODES, D_OUT, 0);
}